// round 4
// baseline (speedup 1.0000x reference)
#include <cuda_runtime.h>

#define BB 16
#define NN 2000
#define DD 128
#define OO 64
#define NL 3
#define NPAD 2048
#define BN (BB*NN)
#define NCH 125
#define CH 16
#define GT 25
#define HSS 36

__device__ float g_h[BN*DD];
__device__ float g_Wh[BN*DD];
__device__ float g_e1[BN];
__device__ float g_e2[BN];
__device__ float g_e2max[BB];
__device__ int   g_perm[BB*NPAD];
__device__ float g_u1[BB*NN];
__device__ float g_u2[BB*NN];
__device__ int   g_k[BN];
__device__ int   g_bucket[BN];
__device__ int   g_off[BB*(NCH+1)];
__device__ float g_chF[BB*NCH*DD];
__device__ float g_chB[BB*NCH*DD];
__device__ float g_chF2[BB*NCH*DD];
__device__ float g_chB2[BB*NCH*DD];
__device__ float g_chFs[BB*NCH];
__device__ float g_chBs[BB*NCH];
__device__ float g_chFs2[BB*NCH];
__device__ float g_chBs2[BB*NCH];

// ---------- f32x2 packed helpers ----------
__device__ __forceinline__ unsigned long long pk2(float lo, float hi) {
    unsigned long long r;
    asm("mov.b64 %0, {%1, %2};" : "=l"(r)
        : "r"(__float_as_uint(lo)), "r"(__float_as_uint(hi)));
    return r;
}
__device__ __forceinline__ void upk2(unsigned long long v, float& lo, float& hi) {
    unsigned int a, b;
    asm("mov.b64 {%0, %1}, %2;" : "=r"(a), "=r"(b) : "l"(v));
    lo = __uint_as_float(a); hi = __uint_as_float(b);
}
__device__ __forceinline__ unsigned long long fma2(unsigned long long a,
                                                   unsigned long long b,
                                                   unsigned long long c) {
    unsigned long long d;
    asm("fma.rn.f32x2 %0, %1, %2, %3;" : "=l"(d) : "l"(a), "l"(b), "l"(c));
    return d;
}

__device__ __forceinline__ void gemm32(const float* __restrict__ M, const float* hs,
                                       int t, int ldm, unsigned long long* acc) {
#pragma unroll 2
    for (int k = 0; k < DD; k++) {
        float wv = M[k*ldm + t];
        unsigned long long w2 = pk2(wv, wv);
        const float4* hp = (const float4*)(hs + k*HSS);
#pragma unroll
        for (int q = 0; q < 8; q++) {
            float4 h4 = hp[q];
            acc[2*q]   = fma2(pk2(h4.x, h4.y), w2, acc[2*q]);
            acc[2*q+1] = fma2(pk2(h4.z, h4.w), w2, acc[2*q+1]);
        }
    }
}

// ---------------- encoder ----------------
__global__ void enc_kernel(const float* __restrict__ coords, const float* __restrict__ w0,
                           const float* __restrict__ b0, const float* __restrict__ w1,
                           const float* __restrict__ b1) {
    __shared__ float hs[DD*HSS];
    __shared__ float cxy[64];
    int t = threadIdx.x;
    int base = blockIdx.x * 32;
    if (t < 64) cxy[t] = coords[(size_t)base*2 + t];
    __syncthreads();
    float w00 = w0[t], w01 = w0[DD + t], bb = b0[t];
#pragma unroll
    for (int i = 0; i < 32; i++)
        hs[t*HSS + i] = fmaxf(fmaf(cxy[2*i], w00, fmaf(cxy[2*i+1], w01, bb)), 0.f);
    __syncthreads();
    unsigned long long acc[16];
    float bv = b1[t];
    unsigned long long b2 = pk2(bv, bv);
#pragma unroll
    for (int q = 0; q < 16; q++) acc[q] = b2;
    gemm32(w1, hs, t, DD, acc);
#pragma unroll
    for (int q = 0; q < 16; q++) {
        float lo, hi; upk2(acc[q], lo, hi);
        int i = 2*q;
        g_h[(size_t)(base + i)*DD + t] = lo;
        g_h[(size_t)(base + i + 1)*DD + t] = hi;
    }
}

// ---------------- Wh = h @ W + fused e1/e2 ----------------
__global__ void whe_kernel(const float* __restrict__ W, const float* __restrict__ a1,
                           const float* __restrict__ a2) {
    __shared__ float hs[DD*HSS];
    __shared__ float red[2][4][32];
    int t = threadIdx.x;              // 128
    int base = blockIdx.x * 32;
#pragma unroll
    for (int i = 0; i < 32; i++) hs[t*HSS + i] = g_h[(size_t)(base + i)*DD + t];
    __syncthreads();
    unsigned long long acc[16];
#pragma unroll
    for (int q = 0; q < 16; q++) acc[q] = 0ull;
    gemm32(W, hs, t, DD, acc);
    float vals[32];
#pragma unroll
    for (int q = 0; q < 16; q++) upk2(acc[q], vals[2*q], vals[2*q+1]);
#pragma unroll
    for (int i = 0; i < 32; i++) g_Wh[(size_t)(base + i)*DD + t] = vals[i];
    float a1t = a1[t], a2t = a2[t];
    int lane = t & 31, w = t >> 5;
#pragma unroll
    for (int i = 0; i < 32; i++) {
        float s1 = vals[i] * a1t, s2 = vals[i] * a2t;
#pragma unroll
        for (int off = 16; off; off >>= 1) {
            s1 += __shfl_xor_sync(0xffffffffu, s1, off);
            s2 += __shfl_xor_sync(0xffffffffu, s2, off);
        }
        if (lane == 0) { red[0][w][i] = s1; red[1][w][i] = s2; }
    }
    __syncthreads();
    if (t < 64) {
        int which = t >> 5, i = t & 31;
        float s = red[which][0][i] + red[which][1][i] + red[which][2][i] + red[which][3][i];
        if (which == 0) g_e1[base + i] = s; else g_e2[base + i] = s;
    }
}

// ---------------- sort + u1/u2 + node bucketing by breakpoint chunk ----------------
__global__ void sort_kernel() {
    __shared__ float sv[NPAD];
    __shared__ int   sp[NPAD];
    __shared__ int   scnt[NCH];
    __shared__ int   soff[NCH+1];
    int b = blockIdx.x, tid = threadIdx.x;      // 1024
    const float INF = __int_as_float(0x7f800000);
    int i0 = 2*tid, i1 = i0 + 1;
    sv[i0] = (i0 < NN) ? g_e2[b*NN + i0] : INF; sp[i0] = i0;
    sv[i1] = (i1 < NN) ? g_e2[b*NN + i1] : INF; sp[i1] = i1;
    if (tid < NCH) scnt[tid] = 0;
    __syncthreads();
    for (int k = 2; k <= NPAD; k <<= 1) {
        for (int j = k >> 1; j >= 64; j >>= 1) {
#pragma unroll
            for (int rep = 0; rep < 2; rep++) {
                int i = tid + rep*1024;
                int ixj = i ^ j;
                if (ixj > i) {
                    bool up = ((i & k) == 0);
                    float a = sv[i], c2 = sv[ixj];
                    if (up ? (a > c2) : (a < c2)) {
                        sv[i] = c2; sv[ixj] = a;
                        int tp = sp[i]; sp[i] = sp[ixj]; sp[ixj] = tp;
                    }
                }
            }
            __syncthreads();
        }
        float v0 = sv[i0], v1 = sv[i1];
        int p0 = sp[i0], p1 = sp[i1];
        bool up = ((i0 & k) == 0);
        int jmax = ((k >> 1) < 32) ? (k >> 1) : 32;
        for (int j = jmax; j >= 2; j >>= 1) {
            int dlt = j >> 1;
            float q0 = __shfl_xor_sync(0xffffffffu, v0, dlt);
            int   r0 = __shfl_xor_sync(0xffffffffu, p0, dlt);
            float q1 = __shfl_xor_sync(0xffffffffu, v1, dlt);
            int   r1 = __shfl_xor_sync(0xffffffffu, p1, dlt);
            bool lower = ((tid & dlt) == 0);
            bool tk0 = (lower == up) ? (q0 < v0) : (q0 > v0);
            bool tk1 = (lower == up) ? (q1 < v1) : (q1 > v1);
            if (tk0) { v0 = q0; p0 = r0; }
            if (tk1) { v1 = q1; p1 = r1; }
        }
        if (up ? (v0 > v1) : (v0 < v1)) {
            float tv = v0; v0 = v1; v1 = tv;
            int tp = p0; p0 = p1; p1 = tp;
        }
        sv[i0] = v0; sp[i0] = p0; sv[i1] = v1; sp[i1] = p1;
        __syncthreads();
    }
    float e2m = sv[NN - 1];
    if (tid == 0) g_e2max[b] = e2m;
#pragma unroll
    for (int rep = 0; rep < 2; rep++) {
        int i = tid + rep*1024;
        g_perm[b*NPAD + i] = sp[i];
        if (i < NN) {
            float ev = sv[i] - e2m;
            g_u1[b*NN + i] = __expf(ev);
            g_u2[b*NN + i] = __expf(0.2f * ev);
        }
    }
    // compute each node's breakpoint k (first idx with e2_sorted >= -e1) + count buckets
    int kreg[2]; int creg[2];
#pragma unroll
    for (int rep = 0; rep < 2; rep++) {
        int i = tid + rep*1024;
        kreg[rep] = -1;
        if (i < NN) {
            float v = -g_e1[b*NN + i];
            int lo = 0, hi = NN;
            while (lo < hi) {
                int mid = (lo + hi) >> 1;
                if (sv[mid] < v) lo = mid + 1; else hi = mid;
            }
            kreg[rep] = lo;
            int c = lo >> 4; if (c > NCH - 1) c = NCH - 1;
            creg[rep] = c;
            g_k[b*NN + i] = lo;
            atomicAdd(&scnt[c], 1);
        }
    }
    __syncthreads();
    if (tid == 0) {
        int s = 0;
        for (int c = 0; c < NCH; c++) { soff[c] = s; s += scnt[c]; }
        soff[NCH] = s;
    }
    __syncthreads();
    if (tid <= NCH) g_off[b*(NCH+1) + tid] = soff[tid];
    if (tid < NCH) scnt[tid] = soff[tid];   // cursors
    __syncthreads();
#pragma unroll
    for (int rep = 0; rep < 2; rep++) {
        int i = tid + rep*1024;
        if (i < NN) {
            int pos = atomicAdd(&scnt[creg[rep]], 1);
            g_bucket[b*NN + pos] = i;
        }
    }
}

// ---------------- scanA: per-chunk (16-elem) sums ----------------
__global__ void scanA_kernel() {
    int b = blockIdx.x / NCH, c = blockIdx.x % NCH;
    int d = threadIdx.x;
    int k0 = c * CH;
    float sF = 0.f, sB = 0.f;
#pragma unroll
    for (int k = k0; k < k0 + CH; k++) {
        int pj = g_perm[b*NPAD + k];
        float w = g_Wh[((size_t)b*NN + pj)*DD + d];
        sF = fmaf(g_u2[b*NN + k], w, sF);
        sB = fmaf(g_u1[b*NN + k], w, sB);
    }
    g_chF[(b*NCH + c)*DD + d] = sF;
    g_chB[(b*NCH + c)*DD + d] = sB;
    if (d == 0) {
        float s = 0.f;
#pragma unroll
        for (int k = k0; k < k0 + CH; k++) s += g_u2[b*NN + k];
        g_chFs[b*NCH + c] = s;
    }
    if (d == 1) {
        float s = 0.f;
#pragma unroll
        for (int k = k0; k < k0 + CH; k++) s += g_u1[b*NN + k];
        g_chBs[b*NCH + c] = s;
    }
}

// ---------------- scanC: chunk-level exclusive scans (register-tiled, out-of-place) ----------------
__global__ void scanC_kernel() {       // grid = BB, block = 256
    __shared__ float sFs[NCH], sBs[NCH];
    int b = blockIdx.x, tid = threadIdx.x;
    if (tid < NCH) sFs[tid] = g_chFs[b*NCH + tid];
    else if (tid >= 128 && tid < 128 + NCH) sBs[tid - 128] = g_chBs[b*NCH + tid - 128];
    __syncthreads();
    if (tid == 0) {
        float s = 0.f;
#pragma unroll 5
        for (int c = 0; c < NCH; c++) { g_chFs2[b*NCH + c] = s; s += sFs[c]; }
    }
    if (tid == 128) {
        float s = 0.f;
#pragma unroll 5
        for (int c = NCH - 1; c >= 0; c--) { g_chBs2[b*NCH + c] = s; s += sBs[c]; }
    }
    bool fwd = tid < 128;
    int d = fwd ? tid : tid - 128;
    float s = 0.f;
    float v[GT];
    for (int tile = 0; tile < 5; tile++) {
        int c0 = fwd ? tile*GT : (4 - tile)*GT;
        if (fwd) {
#pragma unroll
            for (int r = 0; r < GT; r++) v[r] = g_chF[(b*NCH + c0 + r)*DD + d];
#pragma unroll
            for (int r = 0; r < GT; r++) { float x = v[r]; v[r] = s; s += x; }
#pragma unroll
            for (int r = 0; r < GT; r++) g_chF2[(b*NCH + c0 + r)*DD + d] = v[r];
        } else {
#pragma unroll
            for (int r = 0; r < GT; r++) v[r] = g_chB[(b*NCH + c0 + r)*DD + d];
#pragma unroll
            for (int r = GT - 1; r >= 0; r--) { float x = v[r]; v[r] = s; s += x; }
#pragma unroll
            for (int r = 0; r < GT; r++) g_chB2[(b*NCH + c0 + r)*DD + d] = v[r];
        }
    }
}

// ---------------- scanBC: within-chunk prefixes in smem + emit node outputs ----------------
__global__ void scanBC_kernel() {      // grid = BB*NCH, block = 128
    __shared__ float pf[17*DD];        // forward u2-weighted prefix (incl chF2 base)
    __shared__ float pb[17*DD];        // within-chunk u1-weighted prefix (from 0)
    __shared__ float sfs[17], sbs[17];
    __shared__ float su1[CH], su2[CH];
    __shared__ int   sperm[CH];
    int b = blockIdx.x / NCH, c = blockIdx.x % NCH;
    int d = threadIdx.x;
    int k0 = c * CH;
    if (d < CH) {
        su1[d] = g_u1[b*NN + k0 + d];
        su2[d] = g_u2[b*NN + k0 + d];
        sperm[d] = g_perm[b*NPAD + k0 + d];
    }
    __syncthreads();
    float w[CH];
#pragma unroll
    for (int k = 0; k < CH; k++) w[k] = g_Wh[((size_t)b*NN + sperm[k])*DD + d];
    float sF = g_chF2[(b*NCH + c)*DD + d];
    float pB = 0.f;
#pragma unroll
    for (int k = 0; k < CH; k++) {
        pf[k*DD + d] = sF; pb[k*DD + d] = pB;
        sF = fmaf(su2[k], w[k], sF);
        pB = fmaf(su1[k], w[k], pB);
    }
    pf[16*DD + d] = sF; pb[16*DD + d] = pB;
    if (d == 0) {
        float s = g_chFs2[b*NCH + c];
#pragma unroll
        for (int k = 0; k < CH; k++) { sfs[k] = s; s += su2[k]; }
        sfs[16] = s;
    }
    if (d == 1) {
        float s = 0.f;
#pragma unroll
        for (int k = 0; k < CH; k++) { sbs[k] = s; s += su1[k]; }
        sbs[16] = s;
    }
    __syncthreads();
    float chBv  = g_chB[(b*NCH + c)*DD + d];
    float chB2v = g_chB2[(b*NCH + c)*DD + d];
    float chBs_v  = g_chBs[b*NCH + c];
    float chBs2_v = g_chBs2[b*NCH + c];
    float e2m = g_e2max[b];
    int off = g_off[b*(NCH+1) + c];
    int cnt = g_off[b*(NCH+1) + c + 1] - off;
    for (int n = 0; n < cnt; n++) {
        int node = g_bucket[b*NN + off + n];
        int kk = g_k[b*NN + node] - k0;
        float e1 = g_e1[b*NN + node];
        float tt = e1 + e2m;
        float m = fmaxf(tt, 0.2f * tt);
        float alpha = __expf(tt - m);
        float beta  = __expf(0.2f * tt - m);
        float S1s = chBs2_v + (chBs_v - sbs[kk]);
        float P2s = sfs[kk];
        float inv = 1.0f / (alpha * S1s + beta * P2s);
        float S1 = chB2v + (chBv - pb[kk*DD + d]);
        float P2 = pf[kk*DD + d];
        g_h[((size_t)b*NN + node)*DD + d] = fmaxf((alpha * S1 + beta * P2) * inv, 0.f);
    }
}

// ---------------- proj ----------------
__global__ void proj_kernel(const float* __restrict__ pw, const float* __restrict__ pb,
                            float* __restrict__ out) {
    __shared__ float hs[DD*HSS];
    int t = threadIdx.x;              // 64
    int base = blockIdx.x * 32;
    for (int kk = t; kk < DD; kk += 64) {
#pragma unroll
        for (int i = 0; i < 32; i++) hs[kk*HSS + i] = g_h[(size_t)(base + i)*DD + kk];
    }
    __syncthreads();
    unsigned long long acc[16];
    float bv = pb[t];
    unsigned long long b2 = pk2(bv, bv);
#pragma unroll
    for (int q = 0; q < 16; q++) acc[q] = b2;
    gemm32(pw, hs, t, OO, acc);
#pragma unroll
    for (int q = 0; q < 16; q++) {
        float lo, hi; upk2(acc[q], lo, hi);
        int i = 2*q;
        out[(size_t)(base + i)*OO + t] = lo;
        out[(size_t)(base + i + 1)*OO + t] = hi;
    }
}

extern "C" void kernel_launch(void* const* d_in, const int* in_sizes, int n_in,
                              void* d_out, int out_size) {
    const float* coords = (const float*)d_in[0];
    const float* enc_w0 = (const float*)d_in[1];
    const float* enc_b0 = (const float*)d_in[2];
    const float* enc_w1 = (const float*)d_in[3];
    const float* enc_b1 = (const float*)d_in[4];
    const float* gat_W  = (const float*)d_in[5];
    const float* gat_a1 = (const float*)d_in[6];
    const float* gat_a2 = (const float*)d_in[7];
    const float* proj_w = (const float*)d_in[8];
    const float* proj_b = (const float*)d_in[9];
    float* out = (float*)d_out;

    enc_kernel<<<BN/32, 128>>>(coords, enc_w0, enc_b0, enc_w1, enc_b1);
    for (int l = 0; l < NL; l++) {
        whe_kernel<<<BN/32, 128>>>(gat_W + (size_t)l*DD*DD, gat_a1 + l*DD, gat_a2 + l*DD);
        sort_kernel<<<BB, 1024>>>();
        scanA_kernel<<<BB*NCH, 128>>>();
        scanC_kernel<<<BB, 256>>>();
        scanBC_kernel<<<BB*NCH, 128>>>();
    }
    proj_kernel<<<BN/32, 64>>>(proj_w, proj_b, out);
}

// round 5
// speedup vs baseline: 3.4661x; 3.4661x over previous
#include <cuda_runtime.h>

#define BB 16
#define NN 2000
#define DD 128
#define OO 64
#define NL 3
#define NPAD 2048
#define BN (BB*NN)
#define NCH 125
#define CH 16
#define GT 25
#define NP1 (NN+1)
#define HSS 36

__device__ float g_h[BN*DD];
__device__ float g_Wh[BN*DD];
__device__ float g_e1[BN];
__device__ float g_e2[BN];
__device__ float g_e2max[BB];
__device__ int   g_perm[BB*NPAD];
__device__ int   g_k[BN];
__device__ float g_u1[BB*NN];
__device__ float g_u2[BB*NN];
__device__ float g_S1[BB*NP1*DD];
__device__ float g_P2[BB*NP1*DD];
__device__ float g_S1s[BB*NP1];
__device__ float g_P2s[BB*NP1];
__device__ float g_chF[BB*NCH*DD];
__device__ float g_chB[BB*NCH*DD];
__device__ float g_chF2[BB*NCH*DD];
__device__ float g_chB2[BB*NCH*DD];
__device__ float g_chFs[BB*NCH];
__device__ float g_chBs[BB*NCH];
__device__ float g_chFs2[BB*NCH];
__device__ float g_chBs2[BB*NCH];

// ---------- f32x2 packed helpers ----------
__device__ __forceinline__ unsigned long long pk2(float lo, float hi) {
    unsigned long long r;
    asm("mov.b64 %0, {%1, %2};" : "=l"(r)
        : "r"(__float_as_uint(lo)), "r"(__float_as_uint(hi)));
    return r;
}
__device__ __forceinline__ void upk2(unsigned long long v, float& lo, float& hi) {
    unsigned int a, b;
    asm("mov.b64 {%0, %1}, %2;" : "=r"(a), "=r"(b) : "l"(v));
    lo = __uint_as_float(a); hi = __uint_as_float(b);
}
__device__ __forceinline__ unsigned long long fma2(unsigned long long a,
                                                   unsigned long long b,
                                                   unsigned long long c) {
    unsigned long long d;
    asm("fma.rn.f32x2 %0, %1, %2, %3;" : "=l"(d) : "l"(a), "l"(b), "l"(c));
    return d;
}

// monotone float<->uint transform for sorting
__device__ __forceinline__ unsigned int xf(float f) {
    unsigned int u = __float_as_uint(f);
    return (u & 0x80000000u) ? ~u : (u | 0x80000000u);
}
__device__ __forceinline__ float ixf(unsigned int u) {
    unsigned int b = (u & 0x80000000u) ? (u & 0x7FFFFFFFu) : ~u;
    return __uint_as_float(b);
}

__device__ __forceinline__ void gemm32(const float* __restrict__ M, const float* hs,
                                       int t, int ldm, unsigned long long* acc) {
#pragma unroll 2
    for (int k = 0; k < DD; k++) {
        float wv = M[k*ldm + t];
        unsigned long long w2 = pk2(wv, wv);
        const float4* hp = (const float4*)(hs + k*HSS);
#pragma unroll
        for (int q = 0; q < 8; q++) {
            float4 h4 = hp[q];
            acc[2*q]   = fma2(pk2(h4.x, h4.y), w2, acc[2*q]);
            acc[2*q+1] = fma2(pk2(h4.z, h4.w), w2, acc[2*q+1]);
        }
    }
}

// combine prelude: per-node (rb, alpha, beta, 1/Z); k precomputed in sort
__device__ __forceinline__ void combine_prelude(int node, int* s_rb, float* s_alpha,
                                                float* s_beta, float* s_inv, int slot) {
    int b = node / NN;
    float e1 = g_e1[node];
    int k = g_k[node];
    float e2m = g_e2max[b];
    float tt = e1 + e2m;
    float m = fmaxf(tt, 0.2f * tt);
    float alpha = __expf(tt - m);
    float beta  = __expf(0.2f * tt - m);
    int rb = b*NP1 + k;
    float Z = alpha * g_S1s[rb] + beta * g_P2s[rb];
    s_rb[slot] = rb; s_alpha[slot] = alpha; s_beta[slot] = beta; s_inv[slot] = 1.0f / Z;
}

// ---------------- encoder ----------------
__global__ void enc_kernel(const float* __restrict__ coords, const float* __restrict__ w0,
                           const float* __restrict__ b0, const float* __restrict__ w1,
                           const float* __restrict__ b1) {
    __shared__ float hs[DD*HSS];
    __shared__ float cxy[64];
    int t = threadIdx.x;
    int base = blockIdx.x * 32;
    if (t < 64) cxy[t] = coords[(size_t)base*2 + t];
    __syncthreads();
    float w00 = w0[t], w01 = w0[DD + t], bb = b0[t];
#pragma unroll
    for (int i = 0; i < 32; i++)
        hs[t*HSS + i] = fmaxf(fmaf(cxy[2*i], w00, fmaf(cxy[2*i+1], w01, bb)), 0.f);
    __syncthreads();
    unsigned long long acc[16];
    float bv = b1[t];
    unsigned long long b2 = pk2(bv, bv);
#pragma unroll
    for (int q = 0; q < 16; q++) acc[q] = b2;
    gemm32(w1, hs, t, DD, acc);
#pragma unroll
    for (int q = 0; q < 16; q++) {
        float lo, hi; upk2(acc[q], lo, hi);
        int i = 2*q;
        g_h[(size_t)(base + i)*DD + t] = lo;
        g_h[(size_t)(base + i + 1)*DD + t] = hi;
    }
}

// ---------------- Wh = h @ W + fused e1/e2 (+ optional fused combine) ----------------
template<bool FUSED>
__global__ void whe_kernel(const float* __restrict__ W, const float* __restrict__ a1,
                           const float* __restrict__ a2) {
    __shared__ float hs[DD*HSS];
    __shared__ float red[2][4][32];
    __shared__ float s_alpha[32], s_beta[32], s_inv[32];
    __shared__ int s_rb[32];
    int t = threadIdx.x;              // 128
    int base = blockIdx.x * 32;
    if (FUSED) {
        if (t < 32) combine_prelude(base + t, s_rb, s_alpha, s_beta, s_inv, t);
        __syncthreads();
#pragma unroll
        for (int i = 0; i < 32; i++) {
            size_t ro = (size_t)s_rb[i]*DD + t;
            float num = s_alpha[i]*g_S1[ro] + s_beta[i]*g_P2[ro];
            hs[t*HSS + i] = fmaxf(num * s_inv[i], 0.f);
        }
    } else {
#pragma unroll
        for (int i = 0; i < 32; i++) hs[t*HSS + i] = g_h[(size_t)(base + i)*DD + t];
    }
    __syncthreads();
    unsigned long long acc[16];
#pragma unroll
    for (int q = 0; q < 16; q++) acc[q] = 0ull;
    gemm32(W, hs, t, DD, acc);
    float vals[32];
#pragma unroll
    for (int q = 0; q < 16; q++) upk2(acc[q], vals[2*q], vals[2*q+1]);
#pragma unroll
    for (int i = 0; i < 32; i++) g_Wh[(size_t)(base + i)*DD + t] = vals[i];
    float a1t = a1[t], a2t = a2[t];
    int lane = t & 31, w = t >> 5;
#pragma unroll
    for (int i = 0; i < 32; i++) {
        float s1 = vals[i] * a1t, s2 = vals[i] * a2t;
#pragma unroll
        for (int off = 16; off; off >>= 1) {
            s1 += __shfl_xor_sync(0xffffffffu, s1, off);
            s2 += __shfl_xor_sync(0xffffffffu, s2, off);
        }
        if (lane == 0) { red[0][w][i] = s1; red[1][w][i] = s2; }
    }
    __syncthreads();
    if (t < 64) {
        int which = t >> 5, i = t & 31;
        float s = red[which][0][i] + red[which][1][i] + red[which][2][i] + red[which][3][i];
        if (which == 0) g_e1[base + i] = s; else g_e2[base + i] = s;
    }
}

// ---------------- 64-bit packed bitonic sort + u1/u2 + breakpoint k ----------------
__global__ void sort_kernel() {
    __shared__ unsigned long long kv[NPAD];
    int b = blockIdx.x, tid = threadIdx.x;      // 1024
    int i0 = 2*tid, i1 = i0 + 1;
#pragma unroll
    for (int rep = 0; rep < 2; rep++) {
        int i = tid + rep*1024;
        if (i < NN) {
            unsigned int u = xf(g_e2[b*NN + i]);
            kv[i] = ((unsigned long long)u << 32) | (unsigned int)i;
        } else {
            kv[i] = 0xFFFFFFFFFFFFFFFFull;
        }
    }
    __syncthreads();
    for (int k = 2; k <= NPAD; k <<= 1) {
        for (int j = k >> 1; j >= 64; j >>= 1) {
#pragma unroll
            for (int rep = 0; rep < 2; rep++) {
                int i = tid + rep*1024;
                int ixj = i ^ j;
                if (ixj > i) {
                    bool up = ((i & k) == 0);
                    unsigned long long a = kv[i], c2 = kv[ixj];
                    if (up ? (a > c2) : (a < c2)) { kv[i] = c2; kv[ixj] = a; }
                }
            }
            __syncthreads();
        }
        unsigned long long v0 = kv[i0], v1 = kv[i1];
        bool up = ((i0 & k) == 0);
        int jmax = ((k >> 1) < 32) ? (k >> 1) : 32;
        for (int j = jmax; j >= 2; j >>= 1) {
            int dlt = j >> 1;
            unsigned long long q0 = __shfl_xor_sync(0xffffffffu, v0, dlt);
            unsigned long long q1 = __shfl_xor_sync(0xffffffffu, v1, dlt);
            bool lower = ((tid & dlt) == 0);
            if ((lower == up) ? (q0 < v0) : (q0 > v0)) v0 = q0;
            if ((lower == up) ? (q1 < v1) : (q1 > v1)) v1 = q1;
        }
        if (up ? (v0 > v1) : (v0 < v1)) { unsigned long long tv = v0; v0 = v1; v1 = tv; }
        kv[i0] = v0; kv[i1] = v1;
        __syncthreads();
    }
    float e2m = ixf((unsigned int)(kv[NN - 1] >> 32));
    if (tid == 0) g_e2max[b] = e2m;
#pragma unroll
    for (int rep = 0; rep < 2; rep++) {
        int i = tid + rep*1024;
        unsigned long long v = kv[i];
        g_perm[b*NPAD + i] = (int)(v & 0xFFFFFFFFu);
        if (i < NN) {
            float ev = ixf((unsigned int)(v >> 32)) - e2m;
            g_u1[b*NN + i] = __expf(ev);
            g_u2[b*NN + i] = __expf(0.2f * ev);
        }
    }
    // breakpoint: first sorted idx with e2 >= -e1 (search on transformed keys in smem)
#pragma unroll
    for (int rep = 0; rep < 2; rep++) {
        int i = tid + rep*1024;
        if (i < NN) {
            unsigned int uv = xf(-g_e1[b*NN + i]);
            int lo = 0, hi = NN;
            while (lo < hi) {
                int mid = (lo + hi) >> 1;
                if ((unsigned int)(kv[mid] >> 32) < uv) lo = mid + 1; else hi = mid;
            }
            g_k[b*NN + i] = lo;
        }
    }
}

// ---------------- scanA: per-chunk (16-elem) sums ----------------
__global__ void scanA_kernel() {
    __shared__ float su1[CH], su2[CH];
    __shared__ int sperm[CH];
    int b = blockIdx.x / NCH, c = blockIdx.x % NCH;
    int d = threadIdx.x;
    int k0 = c * CH;
    if (d < CH) {
        su1[d] = g_u1[b*NN + k0 + d];
        su2[d] = g_u2[b*NN + k0 + d];
        sperm[d] = g_perm[b*NPAD + k0 + d];
    }
    __syncthreads();
    float sF = 0.f, sB = 0.f;
#pragma unroll
    for (int k = 0; k < CH; k++) {
        float w = g_Wh[((size_t)b*NN + sperm[k])*DD + d];
        sF = fmaf(su2[k], w, sF);
        sB = fmaf(su1[k], w, sB);
    }
    g_chF[(b*NCH + c)*DD + d] = sF;
    g_chB[(b*NCH + c)*DD + d] = sB;
    if (d == 0) {
        float s = 0.f;
#pragma unroll
        for (int k = 0; k < CH; k++) s += su2[k];
        g_chFs[b*NCH + c] = s;
    }
    if (d == 1) {
        float s = 0.f;
#pragma unroll
        for (int k = 0; k < CH; k++) s += su1[k];
        g_chBs[b*NCH + c] = s;
    }
}

// ---------------- scanC: chunk-level exclusive scans (register-tiled, out-of-place) ----------------
__global__ void scanC_kernel() {       // grid = BB, block = 256
    __shared__ float sFs[NCH], sBs[NCH];
    int b = blockIdx.x, tid = threadIdx.x;
    if (tid < NCH) sFs[tid] = g_chFs[b*NCH + tid];
    else if (tid >= 128 && tid < 128 + NCH) sBs[tid - 128] = g_chBs[b*NCH + tid - 128];
    __syncthreads();
    if (tid == 0) {
        float s = 0.f;
#pragma unroll 5
        for (int c = 0; c < NCH; c++) { g_chFs2[b*NCH + c] = s; s += sFs[c]; }
    }
    if (tid == 128) {
        float s = 0.f;
#pragma unroll 5
        for (int c = NCH - 1; c >= 0; c--) { g_chBs2[b*NCH + c] = s; s += sBs[c]; }
    }
    bool fwd = tid < 128;
    int d = fwd ? tid : tid - 128;
    float s = 0.f;
    float v[GT];
    for (int tile = 0; tile < 5; tile++) {
        int c0 = fwd ? tile*GT : (4 - tile)*GT;
        if (fwd) {
#pragma unroll
            for (int r = 0; r < GT; r++) v[r] = g_chF[(b*NCH + c0 + r)*DD + d];
#pragma unroll
            for (int r = 0; r < GT; r++) { float x = v[r]; v[r] = s; s += x; }
#pragma unroll
            for (int r = 0; r < GT; r++) g_chF2[(b*NCH + c0 + r)*DD + d] = v[r];
        } else {
#pragma unroll
            for (int r = 0; r < GT; r++) v[r] = g_chB[(b*NCH + c0 + r)*DD + d];
#pragma unroll
            for (int r = GT - 1; r >= 0; r--) { float x = v[r]; v[r] = s; s += x; }
#pragma unroll
            for (int r = 0; r < GT; r++) g_chB2[(b*NCH + c0 + r)*DD + d] = v[r];
        }
    }
}

// ---------------- scanB: expand to full P2 / S1 (rows loaded once) ----------------
__global__ void scanB_kernel() {
    __shared__ float su1[CH], su2[CH];
    __shared__ int sperm[CH];
    int b = blockIdx.x / NCH, c = blockIdx.x % NCH;
    int d = threadIdx.x;
    int k0 = c * CH;
    if (d < CH) {
        su1[d] = g_u1[b*NN + k0 + d];
        su2[d] = g_u2[b*NN + k0 + d];
        sperm[d] = g_perm[b*NPAD + k0 + d];
    }
    __syncthreads();
    float w[CH];
#pragma unroll
    for (int k = 0; k < CH; k++) w[k] = g_Wh[((size_t)b*NN + sperm[k])*DD + d];
    size_t rowbase = (size_t)b*NP1;
    float s = g_chF2[(b*NCH + c)*DD + d];
#pragma unroll
    for (int k = 0; k < CH; k++) {
        g_P2[(rowbase + k0 + k)*DD + d] = s;
        s = fmaf(su2[k], w[k], s);
    }
    if (c == NCH - 1) g_P2[(rowbase + NN)*DD + d] = s;
    float s1 = g_chB2[(b*NCH + c)*DD + d];
#pragma unroll
    for (int k = CH - 1; k >= 0; k--) {
        g_S1[(rowbase + k0 + k + 1)*DD + d] = s1;
        s1 = fmaf(su1[k], w[k], s1);
    }
    if (c == 0) g_S1[rowbase*DD + d] = s1;
    if (d == 0) {
        float ss = g_chFs2[b*NCH + c];
#pragma unroll
        for (int k = 0; k < CH; k++) {
            g_P2s[b*NP1 + k0 + k] = ss;
            ss += su2[k];
        }
        if (c == NCH - 1) g_P2s[b*NP1 + NN] = ss;
    }
    if (d == 1) {
        float ss = g_chBs2[b*NCH + c];
#pragma unroll
        for (int k = CH - 1; k >= 0; k--) {
            g_S1s[b*NP1 + k0 + k + 1] = ss;
            ss += su1[k];
        }
        if (c == 0) g_S1s[b*NP1] = ss;
    }
}

// ---------------- proj (fused combine) ----------------
__global__ void proj_kernel(const float* __restrict__ pw, const float* __restrict__ pb,
                            float* __restrict__ out) {
    __shared__ float hs[DD*HSS];
    __shared__ float s_alpha[32], s_beta[32], s_inv[32];
    __shared__ int s_rb[32];
    int t = threadIdx.x;              // 64
    int base = blockIdx.x * 32;
    if (t < 32) combine_prelude(base + t, s_rb, s_alpha, s_beta, s_inv, t);
    __syncthreads();
    for (int kk = t; kk < DD; kk += 64) {
#pragma unroll
        for (int i = 0; i < 32; i++) {
            size_t ro = (size_t)s_rb[i]*DD + kk;
            float num = s_alpha[i]*g_S1[ro] + s_beta[i]*g_P2[ro];
            hs[kk*HSS + i] = fmaxf(num * s_inv[i], 0.f);
        }
    }
    __syncthreads();
    unsigned long long acc[16];
    float bv = pb[t];
    unsigned long long b2 = pk2(bv, bv);
#pragma unroll
    for (int q = 0; q < 16; q++) acc[q] = b2;
    gemm32(pw, hs, t, OO, acc);
#pragma unroll
    for (int q = 0; q < 16; q++) {
        float lo, hi; upk2(acc[q], lo, hi);
        int i = 2*q;
        out[(size_t)(base + i)*OO + t] = lo;
        out[(size_t)(base + i + 1)*OO + t] = hi;
    }
}

extern "C" void kernel_launch(void* const* d_in, const int* in_sizes, int n_in,
                              void* d_out, int out_size) {
    const float* coords = (const float*)d_in[0];
    const float* enc_w0 = (const float*)d_in[1];
    const float* enc_b0 = (const float*)d_in[2];
    const float* enc_w1 = (const float*)d_in[3];
    const float* enc_b1 = (const float*)d_in[4];
    const float* gat_W  = (const float*)d_in[5];
    const float* gat_a1 = (const float*)d_in[6];
    const float* gat_a2 = (const float*)d_in[7];
    const float* proj_w = (const float*)d_in[8];
    const float* proj_b = (const float*)d_in[9];
    float* out = (float*)d_out;

    enc_kernel<<<BN/32, 128>>>(coords, enc_w0, enc_b0, enc_w1, enc_b1);
    for (int l = 0; l < NL; l++) {
        if (l == 0)
            whe_kernel<false><<<BN/32, 128>>>(gat_W, gat_a1, gat_a2);
        else
            whe_kernel<true><<<BN/32, 128>>>(gat_W + (size_t)l*DD*DD,
                                             gat_a1 + l*DD, gat_a2 + l*DD);
        sort_kernel<<<BB, 1024>>>();
        scanA_kernel<<<BB*NCH, 128>>>();
        scanC_kernel<<<BB, 256>>>();
        scanB_kernel<<<BB*NCH, 128>>>();
    }
    proj_kernel<<<BN/32, 64>>>(proj_w, proj_b, out);
}